// round 14
// baseline (speedup 1.0000x reference)
#include <cuda_runtime.h>
#include <cuda_fp16.h>
#include <math.h>
#include <stdint.h>

#define BB 64
#define SS 48
#define EE 512
#define HH 512
#define GG 2048           // 4H
#define M0 (SS*BB)        // 3072

typedef unsigned long long ull;

// ---------------- scratch (device globals; no allocation allowed) ----------------
__device__ __half d_xhi[M0*EE];                 // x fp16 hi        [S*B][E]
__device__ __half d_xlo[M0*EE];                 // x fp16 lo
__device__ __half d_xh3[M0*EE];                 // x fp16 hi / 1024
__device__ __half d_wihhi[2*GG*EE];             // w_ih0 fp16 hi
__device__ __half d_wihlo[2*GG*EE];             // w_ih0 fp16 (lo*1024)
__device__ float d_g0[2*M0*GG];                 // layer0 input gates (post-LN)
__device__ float d_raw0[2*BB*GG];               // layer1-input K-split partial 0
__device__ float d_raw1[2*BB*GG];               // layer1-input K-split partial 1
__device__ float d_rawp[3*2*BB*GG];             // recurrence partials [term][dir][b][g]
__device__ float d_h[2*BB*HH];                  // h fp32
__device__ __half d_hhi[2*BB*HH];               // h fp16 hi
__device__ __half d_hlo[2*BB*HH];               // h fp16 lo
__device__ float d_xc[BB*2*HH];                 // concat(hf,hb) layer0 output
__device__ float d_g1[2*BB*GG];                 // layer1 input gates (post-LN)
__device__ ull   d_flags[128*16];               // per-CTA barrier flags (one 128B line each)

#define WLO_SCALE 2048.0f
#define WLO_INV   (1.0f/2048.0f)

// ---------------- f32x2 helpers ----------------
__device__ __forceinline__ ull pack2(float a){
    ull r; asm("mov.b64 %0, {%1, %1};" : "=l"(r) : "f"(a)); return r;
}
__device__ __forceinline__ ull fma2(ull a, ull b, ull c){
    ull d; asm("fma.rn.f32x2 %0, %1, %2, %3;" : "=l"(d) : "l"(a), "l"(b), "l"(c)); return d;
}

// ---------------- mma.sync / ldmatrix helpers ----------------
__device__ __forceinline__ uint32_t smem_u32(const void* p){
    uint32_t a;
    asm("{ .reg .u64 t; cvta.to.shared.u64 t, %1; cvt.u32.u64 %0, t; }" : "=r"(a) : "l"(p));
    return a;
}
__device__ __forceinline__ void ldsm_x4(uint32_t* r, uint32_t addr){
    asm volatile("ldmatrix.sync.aligned.m8n8.x4.shared.b16 {%0,%1,%2,%3}, [%4];"
        : "=r"(r[0]),"=r"(r[1]),"=r"(r[2]),"=r"(r[3]) : "r"(addr));
}
__device__ __forceinline__ void ldsm_x2(uint32_t* r, uint32_t addr){
    asm volatile("ldmatrix.sync.aligned.m8n8.x2.shared.b16 {%0,%1}, [%2];"
        : "=r"(r[0]),"=r"(r[1]) : "r"(addr));
}
__device__ __forceinline__ void mma16816(float* d, const uint32_t* a, const uint32_t* b){
    asm volatile("mma.sync.aligned.m16n8k16.row.col.f32.f16.f16.f32 "
        "{%0,%1,%2,%3},{%4,%5,%6,%7},{%8,%9},{%0,%1,%2,%3};"
        : "+f"(d[0]),"+f"(d[1]),"+f"(d[2]),"+f"(d[3])
        : "r"(a[0]),"r"(a[1]),"r"(a[2]),"r"(a[3]),"r"(b[0]),"r"(b[1]));
}

// ---------------- grid barrier: per-CTA flag lines, contention-free ----------------
__device__ __forceinline__ void gbar2(int cta, ull target){
    __syncthreads();                              // all CTA work (incl. stores) done
    if (threadIdx.x == 0){
        asm volatile("st.release.gpu.global.u64 [%0], %1;"
                     :: "l"(&d_flags[cta*16]), "l"(target) : "memory");
    }
    if (threadIdx.x < 128){
        ull v;
        do {
            asm volatile("ld.acquire.gpu.global.u64 %0, [%1];"
                         : "=l"(v) : "l"(&d_flags[threadIdx.x*16]) : "memory");
        } while (v < target);
    }
    __syncthreads();
}

// ---------------- block reduction (256 threads = 8 warps) ----------------
__device__ __forceinline__ float2 blockReduce2(float s, float s2, float* red){
    #pragma unroll
    for(int o=16;o>0;o>>=1){
        s  += __shfl_down_sync(0xffffffffu, s,  o);
        s2 += __shfl_down_sync(0xffffffffu, s2, o);
    }
    int w = threadIdx.x >> 5, l = threadIdx.x & 31;
    __syncthreads();
    if(l==0){ red[w] = s; red[w+8] = s2; }
    __syncthreads();
    float ts = red[0], ts2 = red[8];
    #pragma unroll
    for(int i=1;i<8;i++){ ts += red[i]; ts2 += red[i+8]; }
    return make_float2(ts, ts2);
}

// ---------------- activations: 1 MUFU (exp) + FFMA Newton reciprocal ----------------
// nrcp: bit-trick seed (~5-10% rel err) + 3 Newton iters (e->e^2): ~1e-8 rel.
// Runs on the FMA pipe, freeing MUFU (rt_SMSP=8) which was the phase-B bottleneck.
__device__ __forceinline__ float nrcp(float d){
    float y = __int_as_float(0x7EF311C3u - __float_as_int(d));
    y = y * __fmaf_rn(-d, y, 2.0f);
    y = y * __fmaf_rn(-d, y, 2.0f);
    y = y * __fmaf_rn(-d, y, 2.0f);
    return y;
}
__device__ __forceinline__ float sigm_f(float x){
    float xa = fminf(fmaxf(x, -30.f), 30.f);      // keep exp finite for nrcp
    return nrcp(1.f + __expf(-xa));
}
__device__ __forceinline__ float tanh_f(float x){
    float xa = fminf(fmaxf(x, -15.f), 15.f);
    float u = __expf(2.f*xa);
    return __fmaf_rn(-2.f, nrcp(u + 1.f), 1.f);
}

// ---------------- permute + fp16 split of x ----------------
__global__ void permute_x(const float* __restrict__ x){
    int i = blockIdx.x*blockDim.x + threadIdx.x;   // 393216 float4
    int e4 = i & 127;
    int m  = i >> 7;
    int s = m / BB, b = m % BB;
    float4 v = ((const float4*)x)[ (size_t)(b*SS + s)*128 + e4 ];
    float f[4] = {v.x, v.y, v.z, v.w};
    __half hi[4], lo[4], h3[4];
    #pragma unroll
    for(int q=0;q<4;q++){
        hi[q] = __float2half(f[q]);
        lo[q] = __float2half(f[q] - __half2float(hi[q]));
        h3[q] = __float2half(__half2float(hi[q]) * 0.0009765625f);  // /1024
    }
    size_t off = (size_t)m*EE + e4*4;
    *(ull*)(d_xhi + off) = *(const ull*)hi;
    *(ull*)(d_xlo + off) = *(const ull*)lo;
    *(ull*)(d_xh3 + off) = *(const ull*)h3;
}

// ---------------- fp16 split of w_ih0 (wlo pre-scaled by 1024) ----------------
__global__ void conv_wih(const float* __restrict__ W){
    int i = blockIdx.x*blockDim.x + threadIdx.x;   // 1M float2
    float2 wv = ((const float2*)W)[i];
    __half h0 = __float2half(wv.x), h1 = __float2half(wv.y);
    __half l0 = __float2half((wv.x - __half2float(h0)) * 1024.0f);
    __half l1 = __float2half((wv.y - __half2float(h1)) * 1024.0f);
    __half2 ph; ph.x = h0; ph.y = h1;
    __half2 pl; pl.x = l0; pl.y = l1;
    *(__half2*)(d_wihhi + (size_t)i*2) = ph;
    *(__half2*)(d_wihlo + (size_t)i*2) = pl;
}

__global__ void copy_concat(int to_out, float* out){
    int b = blockIdx.x, tid = threadIdx.x;
    float* dst = to_out ? (out + (size_t)b*1024) : (d_xc + (size_t)b*1024);
    #pragma unroll
    for(int p=0;p<4;p++){
        int idx = tid + 256*p;
        float v = (idx < HH) ? d_h[(size_t)b*HH + idx]
                             : d_h[(size_t)BB*HH + (size_t)b*HH + (idx-HH)];
        dst[idx] = v;
    }
}

// ---------------- big GEMM: layer0 input gates (HMMA fp16 3-term) ----------------
#define KP2 136                   // padded halves/row (272B: conflict-free ldmatrix)
#define TSZ (128*KP2*2)           // 34816 B per tile
#define G_SMEM (5*TSZ)            // 174080 B
__global__ __launch_bounds__(256,1) void gemm_ih0h(){
    extern __shared__ __align__(16) char gsm[];
    char* tXhi = gsm;
    char* tXlo = gsm + TSZ;
    char* tXh3 = gsm + 2*TSZ;
    char* tWhi = gsm + 3*TSZ;
    char* tWlo = gsm + 4*TSZ;
    uint32_t su = smem_u32(gsm);

    int nt = blockIdx.x, mt = blockIdx.y, dir = blockIdx.z;
    int tid = threadIdx.x, lane = tid & 31, wid = tid >> 5;
    int m0w = (wid >> 1) * 32;
    int n0w = (wid & 1) * 64;

    const __half* gXhi = d_xhi + (size_t)mt*128*EE;
    const __half* gXlo = d_xlo + (size_t)mt*128*EE;
    const __half* gXh3 = d_xh3 + (size_t)mt*128*EE;
    const __half* gWhi = d_wihhi + ((size_t)dir*GG + nt*128)*EE;
    const __half* gWlo = d_wihlo + ((size_t)dir*GG + nt*128)*EE;

    uint32_t aHi = su + 0*TSZ + (uint32_t)(((m0w + (lane & 15))*KP2 + (lane >> 4)*8) * 2);
    uint32_t aLo = aHi + TSZ;
    uint32_t aH3 = aHi + 2*TSZ;
    uint32_t aHi2 = aHi + 16u*KP2*2u;
    uint32_t aLo2 = aLo + 16u*KP2*2u;
    uint32_t aH32 = aH3 + 16u*KP2*2u;
    uint32_t bHi[8], bLo[8];
    #pragma unroll
    for (int j = 0; j < 8; j++){
        uint32_t off = (uint32_t)(((n0w + j*8 + (lane & 7))*KP2 + ((lane >> 3) & 1)*8) * 2);
        bHi[j] = su + 3*TSZ + off;
        bLo[j] = su + 4*TSZ + off;
    }

    float acc[2][8][4];
    #pragma unroll
    for(int gi=0;gi<2;gi++)
        #pragma unroll
        for(int j=0;j<8;j++)
            #pragma unroll
            for(int q=0;q<4;q++) acc[gi][j][q] = 0.f;

    for (int ch = 0; ch < 4; ch++){
        int kc0 = ch * 128;
        if (ch) __syncthreads();
        for (int idx = tid; idx < 4096; idx += 256){
            int row = idx >> 5, c4 = (idx & 31) * 4;
            size_t go = (size_t)row*EE + kc0 + c4;
            uint32_t so = (uint32_t)(row*KP2 + c4)*2;
            *(ull*)(tXhi + so) = *(const ull*)(gXhi + go);
            *(ull*)(tXlo + so) = *(const ull*)(gXlo + go);
            *(ull*)(tXh3 + so) = *(const ull*)(gXh3 + go);
            *(ull*)(tWhi + so) = *(const ull*)(gWhi + go);
            *(ull*)(tWlo + so) = *(const ull*)(gWlo + go);
        }
        __syncthreads();

        #pragma unroll 2
        for (int kk = 0; kk < 128; kk += 16){
            uint32_t k2 = kk*2;
            uint32_t ahi0[4], ahi1[4], alo0[4], alo1[4], ah30[4], ah31[4];
            ldsm_x4(ahi0, aHi + k2);  ldsm_x4(ahi1, aHi2 + k2);
            ldsm_x4(alo0, aLo + k2);  ldsm_x4(alo1, aLo2 + k2);
            ldsm_x4(ah30, aH3 + k2);  ldsm_x4(ah31, aH32 + k2);
            #pragma unroll
            for (int j = 0; j < 8; j++){
                uint32_t b1[2], b2[2];
                ldsm_x2(b1, bHi[j] + k2);
                ldsm_x2(b2, bLo[j] + k2);
                mma16816(acc[0][j], ahi0, b1);
                mma16816(acc[1][j], ahi1, b1);
                mma16816(acc[0][j], alo0, b1);
                mma16816(acc[1][j], alo1, b1);
                mma16816(acc[0][j], ah30, b2);
                mma16816(acc[1][j], ah31, b2);
            }
        }
    }

    float* Cb = d_g0 + ((size_t)dir*M0 + (size_t)mt*128)*GG + nt*128;
    int r = lane >> 2, cp = (lane & 3)*2;
    #pragma unroll
    for (int gi = 0; gi < 2; gi++){
        #pragma unroll
        for (int j = 0; j < 8; j++){
            float* p = Cb + (size_t)(m0w + gi*16 + r)*GG + n0w + j*8 + cp;
            *(float2*)p            = make_float2(acc[gi][j][0], acc[gi][j][1]);
            *(float2*)(p + 8*GG)   = make_float2(acc[gi][j][2], acc[gi][j][3]);
        }
    }
}

// ---------------- glue GEMM for layer1 input gates (once, fp32 f32x2) ----------------
#define LDSS 68
__global__ __launch_bounds__(128) void step_gemm(const float* __restrict__ W, int Ktot){
    __shared__ float As[16*LDSS];
    __shared__ float Bs[16*LDSS];
    int gt = blockIdx.x, ks = blockIdx.y, dir = blockIdx.z;
    int Kc = Ktot >> 1;
    int k0 = ks * Kc;
    const float* Ab = d_xc; int lda = 2*HH;
    const float* Wb = W + ((size_t)dir*GG + gt*64)*Ktot;
    int tid = threadIdx.x;
    int lm = tid >> 2;
    int k4 = (tid & 3) * 4;
    int tm = tid >> 3, tn = tid & 7;
    ull acc[4][4];
    #pragma unroll
    for(int i=0;i<4;i++)
        #pragma unroll
        for(int j=0;j<4;j++) acc[i][j] = 0ull;

    for(int kt=0; kt<Kc; kt+=16){
        float4 a0 = *(const float4*)(Ab + (size_t)lm*lda      + k0 + kt + k4);
        float4 a1 = *(const float4*)(Ab + (size_t)(lm+32)*lda + k0 + kt + k4);
        float4 b0 = *(const float4*)(Wb + (size_t)lm*Ktot      + k0 + kt + k4);
        float4 b1 = *(const float4*)(Wb + (size_t)(lm+32)*Ktot + k0 + kt + k4);
        __syncthreads();
        As[(k4+0)*LDSS+lm]    = a0.x; As[(k4+1)*LDSS+lm]    = a0.y;
        As[(k4+2)*LDSS+lm]    = a0.z; As[(k4+3)*LDSS+lm]    = a0.w;
        As[(k4+0)*LDSS+lm+32] = a1.x; As[(k4+1)*LDSS+lm+32] = a1.y;
        As[(k4+2)*LDSS+lm+32] = a1.z; As[(k4+3)*LDSS+lm+32] = a1.w;
        Bs[(k4+0)*LDSS+lm]    = b0.x; Bs[(k4+1)*LDSS+lm]    = b0.y;
        Bs[(k4+2)*LDSS+lm]    = b0.z; Bs[(k4+3)*LDSS+lm]    = b0.w;
        Bs[(k4+0)*LDSS+lm+32] = b1.x; Bs[(k4+1)*LDSS+lm+32] = b1.y;
        Bs[(k4+2)*LDSS+lm+32] = b1.z; Bs[(k4+3)*LDSS+lm+32] = b1.w;
        __syncthreads();
        #pragma unroll
        for(int k=0;k<16;k++){
            float4 af = *(const float4*)&As[k*LDSS + tm*4];
            ulonglong2 bb0 = *(const ulonglong2*)&Bs[k*LDSS + tn*8];
            ulonglong2 bb1 = *(const ulonglong2*)&Bs[k*LDSS + tn*8 + 4];
            ull bfr[4] = {bb0.x, bb0.y, bb1.x, bb1.y};
            float afr[4] = {af.x, af.y, af.z, af.w};
            #pragma unroll
            for(int i=0;i<4;i++){
                ull aa = pack2(afr[i]);
                #pragma unroll
                for(int j=0;j<4;j++) acc[i][j] = fma2(aa, bfr[j], acc[i][j]);
            }
        }
    }
    float* Ob = (ks ? d_raw1 : d_raw0) + (size_t)dir*BB*GG + gt*64;
    #pragma unroll
    for(int i=0;i<4;i++){
        float* crow = Ob + (size_t)(tm*4+i)*GG + tn*8;
        union { ull u[2]; float4 f; } u0, u1;
        u0.u[0]=acc[i][0]; u0.u[1]=acc[i][1];
        u1.u[0]=acc[i][2]; u1.u[1]=acc[i][3];
        *(float4*)crow     = u0.f;
        *(float4*)(crow+4) = u1.f;
    }
}

// ---------------- row LayerNorm (width 2048) ----------------
__global__ __launch_bounds__(256) void ln_rows(int mode, const float* __restrict__ gam,
                                               const float* __restrict__ bet, int rows_per_dir){
    __shared__ float red[16];
    int row = blockIdx.x, tid = threadIdx.x;
    int dir = row / rows_per_dir;
    const float *s0, *s1 = nullptr; float* dst;
    if(mode==0){ dst = d_g0 + (size_t)row*GG; s0 = dst; }
    else       { s0 = d_raw0 + (size_t)row*GG; s1 = d_raw1 + (size_t)row*GG; dst = d_g1 + (size_t)row*GG; }
    float v[8]; float s=0.f, s2=0.f;
    #pragma unroll
    for(int r=0;r<8;r++){
        int j = tid + 256*r;
        float x = s0[j];
        if(mode) x += s1[j];
        v[r] = x; s += x; s2 += x*x;
    }
    float2 tt = blockReduce2(s, s2, red);
    float mu   = tt.x * (1.f/GG);
    float var  = tt.y * (1.f/GG) - mu*mu;
    float rstd = rsqrtf(var + 1e-5f);
    #pragma unroll
    for(int r=0;r<8;r++){
        int j = tid + 256*r;
        dst[j] = (v[r]-mu)*rstd*gam[dir*GG+j] + bet[dir*GG+j];
    }
}

// ---------------- persistent recurrence kernel: HMMA fp16-split GEMM ----------------
#define KP 520
#define SM_H   133120
#define SM_RED 199680
#define SMEM_DYN (199680 + 64)

__global__ __launch_bounds__(256,1) void lstm_layer(
        int layer, const float* __restrict__ W,
        const float* __restrict__ lnhh_g, const float* __restrict__ lnhh_b,
        const float* __restrict__ lnho_g, const float* __restrict__ lnho_b){
    extern __shared__ __align__(16) char dsm[];
    char* cW = dsm;
    char* cH = dsm + SM_H;
    float* red = (float*)(dsm + SM_RED);
    float* sG  = (float*)(dsm + SM_H);
    uint32_t suW = smem_u32(dsm);
    uint32_t suH = suW + SM_H;

    int cta = blockIdx.x, tid = threadIdx.x;
    int lane = tid & 31, wid = tid >> 5;
    bool active = (cta < 96);
    int term = cta >> 5;
    int rem  = cta & 31;
    int dirA = rem >> 4;
    int gt   = rem & 15;
    int gw = (wid >> 1) * 32;
    int bw = (wid & 1) * 32;
    int dir = cta >> 6;
    int b   = cta & 63;

    // barrier base (flags uniform across CTAs at launch entry)
    __shared__ ull s_base;
    if (tid == 0) s_base = d_flags[cta*16];
    __syncthreads();
    ull tgt = s_base;

    // ---- load W tile once (active CTAs): fp16 hi/lo, padded rows ----
    if (active){
        const float* Wsrc = W + ((size_t)dirA*GG + gt*128)*512;
        for (int c = tid; c < 128*256; c += 256){
            int g  = c >> 8;
            int kc = (c & 255) * 2;
            float2 wv = *(const float2*)(Wsrc + (size_t)g*512 + kc);
            __half e0, e1;
            if (term == 2){
                float h0 = __half2float(__float2half(wv.x));
                float h1 = __half2float(__float2half(wv.y));
                e0 = __float2half((wv.x - h0) * WLO_SCALE);
                e1 = __float2half((wv.y - h1) * WLO_SCALE);
            } else {
                e0 = __float2half(wv.x);
                e1 = __float2half(wv.y);
            }
            __half2 pr; pr.x = e0; pr.y = e1;
            *(__half2*)(cW + ((size_t)g*KP + kc)*2) = pr;
        }
    }

    const __half* hsrc = ((term == 1) ? d_hlo : d_hhi) + (size_t)dirA*BB*HH;
    float* rawOut = d_rawp + (size_t)(term*2 + dirA)*BB*GG;
    const float* r0p = d_rawp + ((size_t)(0*2 + dir)*BB + b)*GG;
    const float* r1p = d_rawp + ((size_t)(1*2 + dir)*BB + b)*GG;
    const float* r2p = d_rawp + ((size_t)(2*2 + dir)*BB + b)*GG;
    float* hout = d_h + ((size_t)dir*BB + b)*HH;
    __half* hhip = d_hhi + ((size_t)dir*BB + b)*HH;
    __half* hlop = d_hlo + ((size_t)dir*BB + b)*HH;

    uint32_t aRow0 = suW + (uint32_t)(((gw + (lane & 15))*KP + (lane >> 4)*8) * 2);
    uint32_t aRow1 = aRow0 + 16u*KP*2u;
    uint32_t bRow[4];
    #pragma unroll
    for (int j = 0; j < 4; j++)
        bRow[j] = suH + (uint32_t)(((bw + j*8 + (lane & 7))*KP + ((lane >> 3) & 1)*8) * 2);

    // ---- step-invariant LN params -> registers (saves 24KB L2 loads per step) ----
    float lgv[8], lbv[8];
    #pragma unroll
    for(int rr=0;rr<8;rr++){
        int j = tid + 256*rr;
        lgv[rr] = lnhh_g[dir*GG+j];
        lbv[rr] = lnhh_b[dir*GG+j];
    }
    float ogv[2], obv[2];
    #pragma unroll
    for(int rr=0;rr<2;rr++){
        int idx = tid + 256*rr;
        ogv[rr] = lnho_g[dir*HH+idx];
        obv[rr] = lnho_b[dir*HH+idx];
    }

    float creg[2] = {0.f, 0.f};

    for (int t = 0; t < SS; ++t){
        if (t > 0){
            if (active){
                for (int c = tid; c < 64*128; c += 256){
                    int bb = c >> 7;
                    int kc = (c & 127) * 4;
                    ull v = __ldcg((const ull*)(hsrc + (size_t)bb*HH + kc));
                    *(ull*)(cH + ((size_t)bb*KP + kc)*2) = v;
                }
                __syncthreads();

                float dacc[2][4][4];
                #pragma unroll
                for(int gi=0;gi<2;gi++)
                    #pragma unroll
                    for(int j=0;j<4;j++)
                        #pragma unroll
                        for(int q=0;q<4;q++) dacc[gi][j][q] = 0.f;

                #pragma unroll 4
                for (int kk = 0; kk < 512; kk += 16){
                    uint32_t af0[4], af1[4];
                    ldsm_x4(af0, aRow0 + kk*2);
                    ldsm_x4(af1, aRow1 + kk*2);
                    uint32_t bf[4][2];
                    #pragma unroll
                    for (int j = 0; j < 4; j++) ldsm_x2(bf[j], bRow[j] + kk*2);
                    #pragma unroll
                    for (int j = 0; j < 4; j++){
                        mma16816(dacc[0][j], af0, bf[j]);
                        mma16816(dacc[1][j], af1, bf[j]);
                    }
                }

                int r = lane >> 2, cp = (lane & 3)*2;
                #pragma unroll
                for (int gi = 0; gi < 2; gi++){
                    #pragma unroll
                    for (int j = 0; j < 4; j++){
                        int g  = gt*128 + gw + gi*16 + r;
                        int bc = bw + j*8 + cp;
                        float* p = rawOut + (size_t)bc*GG + g;
                        p[0]      = dacc[gi][j][0];
                        p[GG]     = dacc[gi][j][1];
                        p[8]      = dacc[gi][j][2];
                        p[GG + 8] = dacc[gi][j][3];
                    }
                }
            }
            tgt += 1; gbar2(cta, tgt);
        }

        // ================= phase B: pointwise =================
        int s_idx = (dir == 0) ? t : (SS-1-t);
        const float* gih = (layer == 0)
            ? d_g0 + ((size_t)dir*M0 + (size_t)s_idx*BB + b)*GG
            : d_g1 + ((size_t)dir*BB + b)*GG;

        float rv[8]; float sm1 = 0.f, sm2 = 0.f;
        if (t > 0){
            #pragma unroll
            for(int rr=0;rr<8;rr++){
                int j = tid + 256*rr;
                float v = __ldcg(r0p + j) + __ldcg(r1p + j) + __ldcg(r2p + j) * WLO_INV;
                rv[rr] = v; sm1 += v; sm2 += v*v;
            }
        } else {
            #pragma unroll
            for(int rr=0;rr<8;rr++) rv[rr] = 0.f;
        }
        __syncthreads();
        float2 tt = blockReduce2(sm1, sm2, red);
        float mu   = tt.x * (1.f/GG);
        float var  = tt.y * (1.f/GG) - mu*mu;
        float rstd = rsqrtf(var + 1e-5f);
        #pragma unroll
        for(int rr=0;rr<8;rr++){
            int j = tid + 256*rr;
            float gate = gih[j] + (rv[rr]-mu)*rstd*lgv[rr] + lbv[rr];
            sG[j] = (j < 3*HH) ? sigm_f(gate) : tanh_f(gate);
        }
        __syncthreads();

        float cs = 0.f, cs2 = 0.f, ov[2];
        #pragma unroll
        for(int rr=0;rr<2;rr++){
            int idx = tid + 256*rr;
            float i_ = sG[idx];
            float f_ = sG[HH   + idx];
            float o_ = sG[2*HH + idx];
            float g_ = sG[3*HH + idx];
            creg[rr] = f_*creg[rr] + i_*g_;
            ov[rr] = o_;
            cs += creg[rr]; cs2 += creg[rr]*creg[rr];
        }
        float2 t2 = blockReduce2(cs, cs2, red);
        float mu2   = t2.x * (1.f/HH);
        float var2  = t2.y * (1.f/HH) - mu2*mu2;
        float rstd2 = rsqrtf(var2 + 1e-5f);
        #pragma unroll
        for(int rr=0;rr<2;rr++){
            int idx = tid + 256*rr;
            float lnc = (creg[rr]-mu2)*rstd2*ogv[rr] + obv[rr];
            float hv = ov[rr]*tanh_f(lnc);
            hout[idx] = hv;
            __half hi = __float2half(hv);
            hhip[idx] = hi;
            hlop[idx] = __float2half(hv - __half2float(hi));
        }
        tgt += 1; gbar2(cta, tgt);
    }
}

// ---------------- launch ----------------
extern "C" void kernel_launch(void* const* d_in, const int* in_sizes, int n_in,
                              void* d_out, int out_size){
    const float* x        = (const float*)d_in[0];
    // d_in[1] = text_length (unused)
    const float* w_ih0    = (const float*)d_in[2];
    const float* w_hh0    = (const float*)d_in[3];
    const float* ln_ih0_g = (const float*)d_in[4];
    const float* ln_ih0_b = (const float*)d_in[5];
    const float* ln_hh0_g = (const float*)d_in[6];
    const float* ln_hh0_b = (const float*)d_in[7];
    const float* ln_ho0_g = (const float*)d_in[8];
    const float* ln_ho0_b = (const float*)d_in[9];
    const float* w_ih1    = (const float*)d_in[10];
    const float* w_hh1    = (const float*)d_in[11];
    const float* ln_ih1_g = (const float*)d_in[12];
    const float* ln_ih1_b = (const float*)d_in[13];
    const float* ln_hh1_g = (const float*)d_in[14];
    const float* ln_hh1_b = (const float*)d_in[15];
    const float* ln_ho1_g = (const float*)d_in[16];
    const float* ln_ho1_b = (const float*)d_in[17];
    float* out = (float*)d_out;

    cudaFuncSetAttribute(lstm_layer, cudaFuncAttributeMaxDynamicSharedMemorySize, SMEM_DYN);
    cudaFuncSetAttribute(gemm_ih0h, cudaFuncAttributeMaxDynamicSharedMemorySize, G_SMEM);

    // phase 0: conversions + layer0 input gates (HMMA)
    permute_x<<<1536,256>>>(x);
    conv_wih<<<4096,256>>>(w_ih0);
    gemm_ih0h<<<dim3(16,24,2),256,G_SMEM>>>();
    ln_rows<<<2*M0,256>>>(0, ln_ih0_g, ln_ih0_b, M0);

    // phase 1: layer0 recurrence (persistent, HMMA fp16-split)
    lstm_layer<<<128,256,SMEM_DYN>>>(0, w_hh0, ln_hh0_g, ln_hh0_b, ln_ho0_g, ln_ho0_b);

    // phase 2: layer1 input gates (once — aliasing bug makes input constant)
    copy_concat<<<BB,256>>>(0, nullptr);
    step_gemm<<<dim3(32,2,2),128>>>(w_ih1, 2*HH);
    ln_rows<<<2*BB,256>>>(1, ln_ih1_g, ln_ih1_b, BB);

    // phase 3: layer1 recurrence (persistent, HMMA fp16-split)
    lstm_layer<<<128,256,SMEM_DYN>>>(1, w_hh1, ln_hh1_g, ln_hh1_b, ln_ho1_g, ln_ho1_b);

    // phase 4: output = concat(hf1, hb1)
    copy_concat<<<BB,256>>>(1, out);
}

// round 17
// speedup vs baseline: 1.0712x; 1.0712x over previous
#include <cuda_runtime.h>
#include <cuda_fp16.h>
#include <math.h>
#include <stdint.h>

#define BB 64
#define SS 48
#define EE 512
#define HH 512
#define GG 2048           // 4H
#define M0 (SS*BB)        // 3072

typedef unsigned long long ull;

// ---------------- scratch (device globals; no allocation allowed) ----------------
__device__ __half d_xhi[M0*EE];                 // x fp16 hi        [S*B][E]
__device__ __half d_xlo[M0*EE];                 // x fp16 lo
__device__ __half d_xh3[M0*EE];                 // x fp16 hi / 1024
__device__ __half d_wihhi[2*GG*EE];             // w_ih0 fp16 hi
__device__ __half d_wihlo[2*GG*EE];             // w_ih0 fp16 (lo*1024)
__device__ float d_g0[2*M0*GG];                 // layer0 input gates (post-LN)
__device__ float d_raw0[2*BB*GG];               // layer1-input K-split partial 0
__device__ float d_raw1[2*BB*GG];               // layer1-input K-split partial 1
__device__ float d_rawp[3*2*BB*GG];             // recurrence partials [term][dir][b][g]
__device__ float d_h[2*BB*HH];                  // h fp32
__device__ __half d_hhi[2*BB*HH];               // h fp16 hi
__device__ __half d_hlo[2*BB*HH];               // h fp16 lo
__device__ float d_xc[BB*2*HH];                 // concat(hf,hb) layer0 output
__device__ float d_g1[2*BB*GG];                 // layer1 input gates (post-LN)
__device__ ull   d_flags[128*16];               // per-CTA barrier flags (one 128B line each)

#define WLO_SCALE 2048.0f
#define WLO_INV   (1.0f/2048.0f)

// ---------------- f32x2 helpers ----------------
__device__ __forceinline__ ull pack2(float a){
    ull r; asm("mov.b64 %0, {%1, %1};" : "=l"(r) : "f"(a)); return r;
}
__device__ __forceinline__ ull fma2(ull a, ull b, ull c){
    ull d; asm("fma.rn.f32x2 %0, %1, %2, %3;" : "=l"(d) : "l"(a), "l"(b), "l"(c)); return d;
}

// ---------------- mma.sync / ldmatrix helpers ----------------
__device__ __forceinline__ uint32_t smem_u32(const void* p){
    uint32_t a;
    asm("{ .reg .u64 t; cvta.to.shared.u64 t, %1; cvt.u32.u64 %0, t; }" : "=r"(a) : "l"(p));
    return a;
}
__device__ __forceinline__ void ldsm_x4(uint32_t* r, uint32_t addr){
    asm volatile("ldmatrix.sync.aligned.m8n8.x4.shared.b16 {%0,%1,%2,%3}, [%4];"
        : "=r"(r[0]),"=r"(r[1]),"=r"(r[2]),"=r"(r[3]) : "r"(addr));
}
__device__ __forceinline__ void ldsm_x2(uint32_t* r, uint32_t addr){
    asm volatile("ldmatrix.sync.aligned.m8n8.x2.shared.b16 {%0,%1}, [%2];"
        : "=r"(r[0]),"=r"(r[1]) : "r"(addr));
}
__device__ __forceinline__ void mma16816(float* d, const uint32_t* a, const uint32_t* b){
    asm volatile("mma.sync.aligned.m16n8k16.row.col.f32.f16.f16.f32 "
        "{%0,%1,%2,%3},{%4,%5,%6,%7},{%8,%9},{%0,%1,%2,%3};"
        : "+f"(d[0]),"+f"(d[1]),"+f"(d[2]),"+f"(d[3])
        : "r"(a[0]),"r"(a[1]),"r"(a[2]),"r"(a[3]),"r"(b[0]),"r"(b[1]));
}

// ---------------- dir-local grid barrier: per-CTA flag lines, 64-CTA groups ----------------
// The fwd (dir0) and bwd (dir1) recurrences share no data; each syncs only its
// own 64-CTA group. Arrival: st.release to OWN flag line; wait: threads 0..63
// each spin-load one group member's flag. Monotone targets, replay-safe.
__device__ __forceinline__ void gbar2(int cta, int group_base, ull target){
    __syncthreads();                              // all CTA work (incl. stores) done
    if (threadIdx.x == 0){
        asm volatile("st.release.gpu.global.u64 [%0], %1;"
                     :: "l"(&d_flags[cta*16]), "l"(target) : "memory");
    }
    if (threadIdx.x < 64){
        ull v;
        do {
            asm volatile("ld.acquire.gpu.global.u64 %0, [%1];"
                         : "=l"(v) : "l"(&d_flags[(group_base + threadIdx.x)*16]) : "memory");
        } while (v < target);
    }
    __syncthreads();
}

// ---------------- block reduction (256 threads = 8 warps) ----------------
__device__ __forceinline__ float2 blockReduce2(float s, float s2, float* red){
    #pragma unroll
    for(int o=16;o>0;o>>=1){
        s  += __shfl_down_sync(0xffffffffu, s,  o);
        s2 += __shfl_down_sync(0xffffffffu, s2, o);
    }
    int w = threadIdx.x >> 5, l = threadIdx.x & 31;
    __syncthreads();
    if(l==0){ red[w] = s; red[w+8] = s2; }
    __syncthreads();
    float ts = red[0], ts2 = red[8];
    #pragma unroll
    for(int i=1;i<8;i++){ ts += red[i]; ts2 += red[i+8]; }
    return make_float2(ts, ts2);
}

__device__ __forceinline__ float sigm_f(float x){
    return __fdividef(1.f, 1.f + __expf(-x));
}
__device__ __forceinline__ float tanh_f(float x){
    float xa = fminf(fmaxf(x, -15.f), 15.f);
    float e = __expf(2.f*xa);
    return __fdividef(e - 1.f, e + 1.f);
}

// ---------------- permute + fp16 split of x ----------------
__global__ void permute_x(const float* __restrict__ x){
    int i = blockIdx.x*blockDim.x + threadIdx.x;   // 393216 float4
    int e4 = i & 127;
    int m  = i >> 7;
    int s = m / BB, b = m % BB;
    float4 v = ((const float4*)x)[ (size_t)(b*SS + s)*128 + e4 ];
    float f[4] = {v.x, v.y, v.z, v.w};
    __half hi[4], lo[4], h3[4];
    #pragma unroll
    for(int q=0;q<4;q++){
        hi[q] = __float2half(f[q]);
        lo[q] = __float2half(f[q] - __half2float(hi[q]));
        h3[q] = __float2half(__half2float(hi[q]) * 0.0009765625f);  // /1024
    }
    size_t off = (size_t)m*EE + e4*4;
    *(ull*)(d_xhi + off) = *(const ull*)hi;
    *(ull*)(d_xlo + off) = *(const ull*)lo;
    *(ull*)(d_xh3 + off) = *(const ull*)h3;
}

// ---------------- fp16 split of w_ih0 (wlo pre-scaled by 1024) ----------------
__global__ void conv_wih(const float* __restrict__ W){
    int i = blockIdx.x*blockDim.x + threadIdx.x;   // 1M float2
    float2 wv = ((const float2*)W)[i];
    __half h0 = __float2half(wv.x), h1 = __float2half(wv.y);
    __half l0 = __float2half((wv.x - __half2float(h0)) * 1024.0f);
    __half l1 = __float2half((wv.y - __half2float(h1)) * 1024.0f);
    __half2 ph; ph.x = h0; ph.y = h1;
    __half2 pl; pl.x = l0; pl.y = l1;
    *(__half2*)(d_wihhi + (size_t)i*2) = ph;
    *(__half2*)(d_wihlo + (size_t)i*2) = pl;
}

__global__ void copy_concat(int to_out, float* out){
    int b = blockIdx.x, tid = threadIdx.x;
    float* dst = to_out ? (out + (size_t)b*1024) : (d_xc + (size_t)b*1024);
    #pragma unroll
    for(int p=0;p<4;p++){
        int idx = tid + 256*p;
        float v = (idx < HH) ? d_h[(size_t)b*HH + idx]
                             : d_h[(size_t)BB*HH + (size_t)b*HH + (idx-HH)];
        dst[idx] = v;
    }
}

// ---------------- big GEMM: layer0 input gates (HMMA fp16 3-term) ----------------
#define KP2 136                   // padded halves/row (272B: conflict-free ldmatrix)
#define TSZ (128*KP2*2)           // 34816 B per tile
#define G_SMEM (5*TSZ)            // 174080 B
__global__ __launch_bounds__(256,1) void gemm_ih0h(){
    extern __shared__ __align__(16) char gsm[];
    char* tXhi = gsm;
    char* tXlo = gsm + TSZ;
    char* tXh3 = gsm + 2*TSZ;
    char* tWhi = gsm + 3*TSZ;
    char* tWlo = gsm + 4*TSZ;
    uint32_t su = smem_u32(gsm);

    int nt = blockIdx.x, mt = blockIdx.y, dir = blockIdx.z;
    int tid = threadIdx.x, lane = tid & 31, wid = tid >> 5;
    int m0w = (wid >> 1) * 32;
    int n0w = (wid & 1) * 64;

    const __half* gXhi = d_xhi + (size_t)mt*128*EE;
    const __half* gXlo = d_xlo + (size_t)mt*128*EE;
    const __half* gXh3 = d_xh3 + (size_t)mt*128*EE;
    const __half* gWhi = d_wihhi + ((size_t)dir*GG + nt*128)*EE;
    const __half* gWlo = d_wihlo + ((size_t)dir*GG + nt*128)*EE;

    uint32_t aHi = su + 0*TSZ + (uint32_t)(((m0w + (lane & 15))*KP2 + (lane >> 4)*8) * 2);
    uint32_t aLo = aHi + TSZ;
    uint32_t aH3 = aHi + 2*TSZ;
    uint32_t aHi2 = aHi + 16u*KP2*2u;
    uint32_t aLo2 = aLo + 16u*KP2*2u;
    uint32_t aH32 = aH3 + 16u*KP2*2u;
    uint32_t bHi[8], bLo[8];
    #pragma unroll
    for (int j = 0; j < 8; j++){
        uint32_t off = (uint32_t)(((n0w + j*8 + (lane & 7))*KP2 + ((lane >> 3) & 1)*8) * 2);
        bHi[j] = su + 3*TSZ + off;
        bLo[j] = su + 4*TSZ + off;
    }

    float acc[2][8][4];
    #pragma unroll
    for(int gi=0;gi<2;gi++)
        #pragma unroll
        for(int j=0;j<8;j++)
            #pragma unroll
            for(int q=0;q<4;q++) acc[gi][j][q] = 0.f;

    for (int ch = 0; ch < 4; ch++){
        int kc0 = ch * 128;
        if (ch) __syncthreads();
        for (int idx = tid; idx < 4096; idx += 256){
            int row = idx >> 5, c4 = (idx & 31) * 4;
            size_t go = (size_t)row*EE + kc0 + c4;
            uint32_t so = (uint32_t)(row*KP2 + c4)*2;
            *(ull*)(tXhi + so) = *(const ull*)(gXhi + go);
            *(ull*)(tXlo + so) = *(const ull*)(gXlo + go);
            *(ull*)(tXh3 + so) = *(const ull*)(gXh3 + go);
            *(ull*)(tWhi + so) = *(const ull*)(gWhi + go);
            *(ull*)(tWlo + so) = *(const ull*)(gWlo + go);
        }
        __syncthreads();

        #pragma unroll 2
        for (int kk = 0; kk < 128; kk += 16){
            uint32_t k2 = kk*2;
            uint32_t ahi0[4], ahi1[4], alo0[4], alo1[4], ah30[4], ah31[4];
            ldsm_x4(ahi0, aHi + k2);  ldsm_x4(ahi1, aHi2 + k2);
            ldsm_x4(alo0, aLo + k2);  ldsm_x4(alo1, aLo2 + k2);
            ldsm_x4(ah30, aH3 + k2);  ldsm_x4(ah31, aH32 + k2);
            #pragma unroll
            for (int j = 0; j < 8; j++){
                uint32_t b1[2], b2[2];
                ldsm_x2(b1, bHi[j] + k2);
                ldsm_x2(b2, bLo[j] + k2);
                mma16816(acc[0][j], ahi0, b1);
                mma16816(acc[1][j], ahi1, b1);
                mma16816(acc[0][j], alo0, b1);
                mma16816(acc[1][j], alo1, b1);
                mma16816(acc[0][j], ah30, b2);
                mma16816(acc[1][j], ah31, b2);
            }
        }
    }

    float* Cb = d_g0 + ((size_t)dir*M0 + (size_t)mt*128)*GG + nt*128;
    int r = lane >> 2, cp = (lane & 3)*2;
    #pragma unroll
    for (int gi = 0; gi < 2; gi++){
        #pragma unroll
        for (int j = 0; j < 8; j++){
            float* p = Cb + (size_t)(m0w + gi*16 + r)*GG + n0w + j*8 + cp;
            *(float2*)p            = make_float2(acc[gi][j][0], acc[gi][j][1]);
            *(float2*)(p + 8*GG)   = make_float2(acc[gi][j][2], acc[gi][j][3]);
        }
    }
}

// ---------------- glue GEMM for layer1 input gates (once, fp32 f32x2) ----------------
#define LDSS 68
__global__ __launch_bounds__(128) void step_gemm(const float* __restrict__ W, int Ktot){
    __shared__ float As[16*LDSS];
    __shared__ float Bs[16*LDSS];
    int gt = blockIdx.x, ks = blockIdx.y, dir = blockIdx.z;
    int Kc = Ktot >> 1;
    int k0 = ks * Kc;
    const float* Ab = d_xc; int lda = 2*HH;
    const float* Wb = W + ((size_t)dir*GG + gt*64)*Ktot;
    int tid = threadIdx.x;
    int lm = tid >> 2;
    int k4 = (tid & 3) * 4;
    int tm = tid >> 3, tn = tid & 7;
    ull acc[4][4];
    #pragma unroll
    for(int i=0;i<4;i++)
        #pragma unroll
        for(int j=0;j<4;j++) acc[i][j] = 0ull;

    for(int kt=0; kt<Kc; kt+=16){
        float4 a0 = *(const float4*)(Ab + (size_t)lm*lda      + k0 + kt + k4);
        float4 a1 = *(const float4*)(Ab + (size_t)(lm+32)*lda + k0 + kt + k4);
        float4 b0 = *(const float4*)(Wb + (size_t)lm*Ktot      + k0 + kt + k4);
        float4 b1 = *(const float4*)(Wb + (size_t)(lm+32)*Ktot + k0 + kt + k4);
        __syncthreads();
        As[(k4+0)*LDSS+lm]    = a0.x; As[(k4+1)*LDSS+lm]    = a0.y;
        As[(k4+2)*LDSS+lm]    = a0.z; As[(k4+3)*LDSS+lm]    = a0.w;
        As[(k4+0)*LDSS+lm+32] = a1.x; As[(k4+1)*LDSS+lm+32] = a1.y;
        As[(k4+2)*LDSS+lm+32] = a1.z; As[(k4+3)*LDSS+lm+32] = a1.w;
        Bs[(k4+0)*LDSS+lm]    = b0.x; Bs[(k4+1)*LDSS+lm]    = b0.y;
        Bs[(k4+2)*LDSS+lm]    = b0.z; Bs[(k4+3)*LDSS+lm]    = b0.w;
        Bs[(k4+0)*LDSS+lm+32] = b1.x; Bs[(k4+1)*LDSS+lm+32] = b1.y;
        Bs[(k4+2)*LDSS+lm+32] = b1.z; Bs[(k4+3)*LDSS+lm+32] = b1.w;
        __syncthreads();
        #pragma unroll
        for(int k=0;k<16;k++){
            float4 af = *(const float4*)&As[k*LDSS + tm*4];
            ulonglong2 bb0 = *(const ulonglong2*)&Bs[k*LDSS + tn*8];
            ulonglong2 bb1 = *(const ulonglong2*)&Bs[k*LDSS + tn*8 + 4];
            ull bfr[4] = {bb0.x, bb0.y, bb1.x, bb1.y};
            float afr[4] = {af.x, af.y, af.z, af.w};
            #pragma unroll
            for(int i=0;i<4;i++){
                ull aa = pack2(afr[i]);
                #pragma unroll
                for(int j=0;j<4;j++) acc[i][j] = fma2(aa, bfr[j], acc[i][j]);
            }
        }
    }
    float* Ob = (ks ? d_raw1 : d_raw0) + (size_t)dir*BB*GG + gt*64;
    #pragma unroll
    for(int i=0;i<4;i++){
        float* crow = Ob + (size_t)(tm*4+i)*GG + tn*8;
        union { ull u[2]; float4 f; } u0, u1;
        u0.u[0]=acc[i][0]; u0.u[1]=acc[i][1];
        u1.u[0]=acc[i][2]; u1.u[1]=acc[i][3];
        *(float4*)crow     = u0.f;
        *(float4*)(crow+4) = u1.f;
    }
}

// ---------------- row LayerNorm (width 2048) ----------------
__global__ __launch_bounds__(256) void ln_rows(int mode, const float* __restrict__ gam,
                                               const float* __restrict__ bet, int rows_per_dir){
    __shared__ float red[16];
    int row = blockIdx.x, tid = threadIdx.x;
    int dir = row / rows_per_dir;
    const float *s0, *s1 = nullptr; float* dst;
    if(mode==0){ dst = d_g0 + (size_t)row*GG; s0 = dst; }
    else       { s0 = d_raw0 + (size_t)row*GG; s1 = d_raw1 + (size_t)row*GG; dst = d_g1 + (size_t)row*GG; }
    float v[8]; float s=0.f, s2=0.f;
    #pragma unroll
    for(int r=0;r<8;r++){
        int j = tid + 256*r;
        float x = s0[j];
        if(mode) x += s1[j];
        v[r] = x; s += x; s2 += x*x;
    }
    float2 tt = blockReduce2(s, s2, red);
    float mu   = tt.x * (1.f/GG);
    float var  = tt.y * (1.f/GG) - mu*mu;
    float rstd = rsqrtf(var + 1e-5f);
    #pragma unroll
    for(int r=0;r<8;r++){
        int j = tid + 256*r;
        dst[j] = (v[r]-mu)*rstd*gam[dir*GG+j] + bet[dir*GG+j];
    }
}

// ---------------- persistent recurrence kernel: HMMA fp16-split GEMM ----------------
// cta = dir*64 + w. Phase A (w<48): term=w>>4, gt=w&15, SAME dir as phase B.
// Phase B: b=w. Each dir forms a closed 64-CTA group -> dir-local barriers.
#define KP 520
#define SM_H   133120
#define SM_RED 199680
#define SMEM_DYN (199680 + 64)

__global__ __launch_bounds__(256,1) void lstm_layer(
        int layer, const float* __restrict__ W,
        const float* __restrict__ lnhh_g, const float* __restrict__ lnhh_b,
        const float* __restrict__ lnho_g, const float* __restrict__ lnho_b){
    extern __shared__ __align__(16) char dsm[];
    char* cW = dsm;
    char* cH = dsm + SM_H;
    float* red = (float*)(dsm + SM_RED);
    float* sG  = (float*)(dsm + SM_H);
    uint32_t suW = smem_u32(dsm);
    uint32_t suH = suW + SM_H;

    int cta = blockIdx.x, tid = threadIdx.x;
    int lane = tid & 31, wid = tid >> 5;
    int dir = cta >> 6;               // both phases
    int w   = cta & 63;
    bool active = (w < 48);
    int term = w >> 4;                // 0..2 when active
    int gt   = w & 15;
    int gw = (wid >> 1) * 32;
    int bw = (wid & 1) * 32;
    int b   = w;                      // phase-B row
    int gbase = dir*64;               // dir-local barrier group

    // barrier base (flags uniform across CTAs at launch entry)
    __shared__ ull s_base;
    if (tid == 0) s_base = d_flags[cta*16];
    __syncthreads();
    ull tgt = s_base;

    // ---- load W tile once (active CTAs): fp16 hi/lo, padded rows ----
    if (active){
        const float* Wsrc = W + ((size_t)dir*GG + gt*128)*512;
        for (int c = tid; c < 128*256; c += 256){
            int g  = c >> 8;
            int kc = (c & 255) * 2;
            float2 wv = *(const float2*)(Wsrc + (size_t)g*512 + kc);
            __half e0, e1;
            if (term == 2){
                float h0 = __half2float(__float2half(wv.x));
                float h1 = __half2float(__float2half(wv.y));
                e0 = __float2half((wv.x - h0) * WLO_SCALE);
                e1 = __float2half((wv.y - h1) * WLO_SCALE);
            } else {
                e0 = __float2half(wv.x);
                e1 = __float2half(wv.y);
            }
            __half2 pr; pr.x = e0; pr.y = e1;
            *(__half2*)(cW + ((size_t)g*KP + kc)*2) = pr;
        }
    }

    const __half* hsrc = ((term == 1) ? d_hlo : d_hhi) + (size_t)dir*BB*HH;
    float* rawOut = d_rawp + (size_t)(term*2 + dir)*BB*GG;
    const float* r0p = d_rawp + ((size_t)(0*2 + dir)*BB + b)*GG;
    const float* r1p = d_rawp + ((size_t)(1*2 + dir)*BB + b)*GG;
    const float* r2p = d_rawp + ((size_t)(2*2 + dir)*BB + b)*GG;
    float* hout = d_h + ((size_t)dir*BB + b)*HH;
    __half* hhip = d_hhi + ((size_t)dir*BB + b)*HH;
    __half* hlop = d_hlo + ((size_t)dir*BB + b)*HH;

    uint32_t aRow0 = suW + (uint32_t)(((gw + (lane & 15))*KP + (lane >> 4)*8) * 2);
    uint32_t aRow1 = aRow0 + 16u*KP*2u;
    uint32_t bRow[4];
    #pragma unroll
    for (int j = 0; j < 4; j++)
        bRow[j] = suH + (uint32_t)(((bw + j*8 + (lane & 7))*KP + ((lane >> 3) & 1)*8) * 2);

    float creg[2] = {0.f, 0.f};

    for (int t = 0; t < SS; ++t){
        if (t > 0){
            if (active){
                for (int c = tid; c < 64*128; c += 256){
                    int bb = c >> 7;
                    int kc = (c & 127) * 4;
                    ull v = __ldcg((const ull*)(hsrc + (size_t)bb*HH + kc));
                    *(ull*)(cH + ((size_t)bb*KP + kc)*2) = v;
                }
                __syncthreads();

                float dacc[2][4][4];
                #pragma unroll
                for(int gi=0;gi<2;gi++)
                    #pragma unroll
                    for(int j=0;j<4;j++)
                        #pragma unroll
                        for(int q=0;q<4;q++) dacc[gi][j][q] = 0.f;

                #pragma unroll 4
                for (int kk = 0; kk < 512; kk += 16){
                    uint32_t af0[4], af1[4];
                    ldsm_x4(af0, aRow0 + kk*2);
                    ldsm_x4(af1, aRow1 + kk*2);
                    uint32_t bf[4][2];
                    #pragma unroll
                    for (int j = 0; j < 4; j++) ldsm_x2(bf[j], bRow[j] + kk*2);
                    #pragma unroll
                    for (int j = 0; j < 4; j++){
                        mma16816(dacc[0][j], af0, bf[j]);
                        mma16816(dacc[1][j], af1, bf[j]);
                    }
                }

                int r = lane >> 2, cp = (lane & 3)*2;
                #pragma unroll
                for (int gi = 0; gi < 2; gi++){
                    #pragma unroll
                    for (int j = 0; j < 4; j++){
                        int g  = gt*128 + gw + gi*16 + r;
                        int bc = bw + j*8 + cp;
                        float* p = rawOut + (size_t)bc*GG + g;
                        p[0]      = dacc[gi][j][0];
                        p[GG]     = dacc[gi][j][1];
                        p[8]      = dacc[gi][j][2];
                        p[GG + 8] = dacc[gi][j][3];
                    }
                }
            }
            tgt += 1; gbar2(cta, gbase, tgt);
        }

        // ================= phase B: pointwise =================
        int s_idx = (dir == 0) ? t : (SS-1-t);
        const float* gih = (layer == 0)
            ? d_g0 + ((size_t)dir*M0 + (size_t)s_idx*BB + b)*GG
            : d_g1 + ((size_t)dir*BB + b)*GG;

        float rv[8]; float sm1 = 0.f, sm2 = 0.f;
        if (t > 0){
            #pragma unroll
            for(int rr=0;rr<8;rr++){
                int j = tid + 256*rr;
                float v = __ldcg(r0p + j) + __ldcg(r1p + j) + __ldcg(r2p + j) * WLO_INV;
                rv[rr] = v; sm1 += v; sm2 += v*v;
            }
        } else {
            #pragma unroll
            for(int rr=0;rr<8;rr++) rv[rr] = 0.f;
        }
        __syncthreads();
        float2 tt = blockReduce2(sm1, sm2, red);
        float mu   = tt.x * (1.f/GG);
        float var  = tt.y * (1.f/GG) - mu*mu;
        float rstd = rsqrtf(var + 1e-5f);
        #pragma unroll
        for(int rr=0;rr<8;rr++){
            int j = tid + 256*rr;
            float gate = __ldcs(gih + j) + (rv[rr]-mu)*rstd*lnhh_g[dir*GG+j] + lnhh_b[dir*GG+j];
            sG[j] = (j < 3*HH) ? sigm_f(gate) : tanh_f(gate);
        }
        __syncthreads();

        float cs = 0.f, cs2 = 0.f, ov[2];
        #pragma unroll
        for(int rr=0;rr<2;rr++){
            int idx = tid + 256*rr;
            float i_ = sG[idx];
            float f_ = sG[HH   + idx];
            float o_ = sG[2*HH + idx];
            float g_ = sG[3*HH + idx];
            creg[rr] = f_*creg[rr] + i_*g_;
            ov[rr] = o_;
            cs += creg[rr]; cs2 += creg[rr]*creg[rr];
        }
        float2 t2 = blockReduce2(cs, cs2, red);
        float mu2   = t2.x * (1.f/HH);
        float var2  = t2.y * (1.f/HH) - mu2*mu2;
        float rstd2 = rsqrtf(var2 + 1e-5f);
        #pragma unroll
        for(int rr=0;rr<2;rr++){
            int idx = tid + 256*rr;
            float lnc = (creg[rr]-mu2)*rstd2*lnho_g[dir*HH+idx] + lnho_b[dir*HH+idx];
            float hv = ov[rr]*tanh_f(lnc);
            hout[idx] = hv;
            __half hi = __float2half(hv);
            hhip[idx] = hi;
            hlop[idx] = __float2half(hv - __half2float(hi));
        }
        tgt += 1; gbar2(cta, gbase, tgt);
    }
}

// ---------------- launch ----------------
extern "C" void kernel_launch(void* const* d_in, const int* in_sizes, int n_in,
                              void* d_out, int out_size){
    const float* x        = (const float*)d_in[0];
    // d_in[1] = text_length (unused)
    const float* w_ih0    = (const float*)d_in[2];
    const float* w_hh0    = (const float*)d_in[3];
    const float* ln_ih0_g = (const float*)d_in[4];
    const float* ln_ih0_b = (const float*)d_in[5];
    const float* ln_hh0_g = (const float*)d_in[6];
    const float* ln_hh0_b = (const float*)d_in[7];
    const float* ln_ho0_g = (const float*)d_in[8];
    const float* ln_ho0_b = (const float*)d_in[9];
    const float* w_ih1    = (const float*)d_in[10];
    const float* w_hh1    = (const float*)d_in[11];
    const float* ln_ih1_g = (const float*)d_in[12];
    const float* ln_ih1_b = (const float*)d_in[13];
    const float* ln_hh1_g = (const float*)d_in[14];
    const float* ln_hh1_b = (const float*)d_in[15];
    const float* ln_ho1_g = (const float*)d_in[16];
    const float* ln_ho1_b = (const float*)d_in[17];
    float* out = (float*)d_out;

    cudaFuncSetAttribute(lstm_layer, cudaFuncAttributeMaxDynamicSharedMemorySize, SMEM_DYN);
    cudaFuncSetAttribute(gemm_ih0h, cudaFuncAttributeMaxDynamicSharedMemorySize, G_SMEM);

    // phase 0: conversions + layer0 input gates (HMMA)
    permute_x<<<1536,256>>>(x);
    conv_wih<<<4096,256>>>(w_ih0);
    gemm_ih0h<<<dim3(16,24,2),256,G_SMEM>>>();
    ln_rows<<<2*M0,256>>>(0, ln_ih0_g, ln_ih0_b, M0);

    // phase 1: layer0 recurrence (persistent, HMMA fp16-split, dir-local barriers)
    lstm_layer<<<128,256,SMEM_DYN>>>(0, w_hh0, ln_hh0_g, ln_hh0_b, ln_ho0_g, ln_ho0_b);

    // phase 2: layer1 input gates (once — aliasing bug makes input constant)
    copy_concat<<<BB,256>>>(0, nullptr);
    step_gemm<<<dim3(32,2,2),128>>>(w_ih1, 2*HH);
    ln_rows<<<2*BB,256>>>(1, ln_ih1_g, ln_ih1_b, BB);

    // phase 3: layer1 recurrence (persistent, HMMA fp16-split, dir-local barriers)
    lstm_layer<<<128,256,SMEM_DYN>>>(1, w_hh1, ln_hh1_g, ln_hh1_b, ln_ho1_g, ln_ho1_b);

    // phase 4: output = concat(hf1, hb1)
    copy_concat<<<BB,256>>>(1, out);
}